// round 1
// baseline (speedup 1.0000x reference)
#include <cuda_runtime.h>
#include <stdint.h>

#define BATCH 2
#define CH 6
#define DD 64
#define HH 96
#define WW 96
#define NSP (DD*HH*WW)        // 589824 spatial locations per batch
#define TOPK 2048
#define NB 4096               // histogram buckets (top 12 bits of flipped key)
#define CAP 4096              // candidate capacity (expected ~2.6K)
#define NW (TOPK/64)          // 32 mask words per row
#define ANCHOR 12.0f

// ---- device scratch (no allocations allowed) ----
__device__ unsigned int       g_hist[BATCH][NB];
__device__ int                g_cnt[BATCH];
__device__ unsigned int       g_tb[BATCH];
__device__ unsigned long long g_cand[BATCH][CAP];
__device__ float4             g_boxA[BATCH][TOPK];   // lo.z, lo.y, lo.x, hi.z
__device__ float4             g_boxB[BATCH][TOPK];   // hi.y, hi.x, vol, pad
__device__ unsigned long long g_mask[BATCH][TOPK][NW];
__device__ unsigned long long g_keep[BATCH][NW];

// monotone fp32 -> u32 key
__device__ __forceinline__ unsigned int fkey(float f) {
    unsigned int u = __float_as_uint(f);
    return u ^ (((unsigned int)((int)u >> 31)) | 0x80000000u);
}
__device__ __forceinline__ float unflip(unsigned int k) {
    unsigned int u = (k & 0x80000000u) ? (k ^ 0x80000000u) : ~k;
    return __uint_as_float(u);
}

__global__ void k_init() {
    int t = blockIdx.x * blockDim.x + threadIdx.x;
    if (t < BATCH * NB) ((unsigned int*)g_hist)[t] = 0u;
    if (t < BATCH) g_cnt[t] = 0;
}

__global__ void k_hist(const float* __restrict__ sc) {
    __shared__ unsigned int h[NB];
    int b = blockIdx.y;
    for (int k = threadIdx.x; k < NB; k += blockDim.x) h[k] = 0u;
    __syncthreads();
    int stride = gridDim.x * blockDim.x;
    const float* s = sc + (size_t)b * NSP;
    for (int i = blockIdx.x * blockDim.x + threadIdx.x; i < NSP; i += stride)
        atomicAdd(&h[fkey(s[i]) >> 20], 1u);
    __syncthreads();
    for (int k = threadIdx.x; k < NB; k += blockDim.x)
        if (h[k]) atomicAdd(&g_hist[b][k], h[k]);
}

// find smallest bucket tb such that sum over buckets >= tb is >= TOPK
__global__ void k_select() {
    __shared__ unsigned int sh[NB];
    __shared__ unsigned int gs[1024];
    int b = blockIdx.x;
    int tid = threadIdx.x;
    for (int k = tid; k < NB; k += 1024) sh[k] = g_hist[b][k];
    __syncthreads();
    unsigned int mysum = sh[4*tid] + sh[4*tid+1] + sh[4*tid+2] + sh[4*tid+3];
    gs[tid] = mysum;
    __syncthreads();
    for (int off = 1; off < 1024; off <<= 1) {
        unsigned int v = gs[tid];
        unsigned int add = (tid + off < 1024) ? gs[tid + off] : 0u;
        __syncthreads();
        gs[tid] = v + add;
        __syncthreads();
    }
    unsigned int S = gs[tid];                      // suffix sum incl. group tid
    unsigned int Snext = (tid < 1023) ? gs[tid + 1] : 0u;
    if (S >= TOPK && Snext < TOPK) {
        unsigned int cum = Snext;
        for (int bk = 4*tid + 3; bk >= 4*tid; bk--) {
            cum += sh[bk];
            if (cum >= TOPK) { g_tb[b] = (unsigned int)bk; break; }
        }
    }
}

__global__ void k_compact(const float* __restrict__ sc) {
    int b = blockIdx.y;
    unsigned int tb = g_tb[b];
    int stride = gridDim.x * blockDim.x;
    const float* s = sc + (size_t)b * NSP;
    for (int i = blockIdx.x * blockDim.x + threadIdx.x; i < NSP; i += stride) {
        unsigned int key = fkey(s[i]);
        if ((key >> 20) >= tb) {
            int pos = atomicAdd(&g_cnt[b], 1);
            if (pos < CAP)
                g_cand[b][pos] = ((unsigned long long)(~key) << 32) | (unsigned int)i;
        }
    }
}

// bitonic sort CAP candidates ascending on (~key, idx) -> top-2048 sorted by
// score desc, tie: lower idx first (matches jax.lax.top_k). Then gather boxes.
__global__ void k_sortgather(const float* __restrict__ bb, float* __restrict__ out) {
    __shared__ unsigned long long a[CAP];   // 32 KB
    int b = blockIdx.x;
    int tid = threadIdx.x;
    int cnt = g_cnt[b]; if (cnt > CAP) cnt = CAP;
    for (int k = tid; k < CAP; k += blockDim.x)
        a[k] = (k < cnt) ? g_cand[b][k] : 0xFFFFFFFFFFFFFFFFull;
    __syncthreads();
    for (int k = 2; k <= CAP; k <<= 1)
        for (int j = k >> 1; j > 0; j >>= 1) {
            for (int i = tid; i < CAP; i += blockDim.x) {
                int ixj = i ^ j;
                if (ixj > i) {
                    unsigned long long x = a[i], y = a[ixj];
                    bool up = ((i & k) == 0);
                    if ((x > y) == up) { a[i] = y; a[ixj] = x; }
                }
            }
            __syncthreads();
        }
    // gather + deparametrize + stage output rows
    for (int t = tid; t < TOPK; t += blockDim.x) {
        unsigned long long e = a[t];
        unsigned int key = ~(unsigned int)(e >> 32);
        unsigned int idx = (unsigned int)e;
        float score = unflip(key);
        int c  = idx / (HH*WW);
        int rm = idx - c * (HH*WW);
        int h  = rm / WW;
        int w  = rm - h * WW;
        const float* base = bb + (size_t)b * CH * NSP + idx;
        float z = base[0]       * ANCHOR + ((float)c + 0.5f);
        float y = base[NSP]     * ANCHOR + ((float)h + 0.5f);
        float x = base[2*NSP]   * ANCHOR + ((float)w + 0.5f);
        float sd = expf(base[3*NSP]) * ANCHOR;
        float sh = expf(base[4*NSP]) * ANCHOR;
        float sw = expf(base[5*NSP]) * ANCHOR;
        float4 A, Bv;
        A.x = z - sd*0.5f; A.y = y - sh*0.5f; A.z = x - sw*0.5f; A.w = z + sd*0.5f;
        Bv.x = y + sh*0.5f; Bv.y = x + sw*0.5f; Bv.z = (sd*sh)*sw; Bv.w = 0.0f;
        g_boxA[b][t] = A; g_boxB[b][t] = Bv;
        float* o = out + ((size_t)b * TOPK + t) * 7;
        o[0] = score; o[1] = z; o[2] = y; o[3] = x; o[4] = sd; o[5] = sh; o[6] = sw;
    }
}

// suppression bitmask: mask[i][w] bit jj set iff IoU(i, j=64w+jj) > 0.25 and j > i
__global__ void k_mask() {
    __shared__ float4 sA[512], sB[512];     // 16 KB j-tile
    int b   = blockIdx.y;
    int tid = threadIdx.x;
    int il  = tid >> 3;                     // 0..31
    int wt  = tid & 7;                      // 0..7
    int i   = blockIdx.x * 32 + il;
    float4 A = g_boxA[b][i], Bv = g_boxB[b][i];
    for (int jt = 0; jt < 4; jt++) {
        __syncthreads();
        for (int k = tid; k < 512; k += 256) {
            sA[k] = g_boxA[b][jt*512 + k];
            sB[k] = g_boxB[b][jt*512 + k];
        }
        __syncthreads();
        int w = jt*8 + wt;
        unsigned long long bits = 0ull;
        if (64*w + 63 > i) {                // some j > i exists in this word
            #pragma unroll 4
            for (int jj = 0; jj < 64; jj++) {
                int jl = wt*64 + jj;
                int j  = jt*512 + jl;
                float4 a2 = sA[jl]; float4 b2 = sB[jl];
                float dz = fminf(A.w,  a2.w) - fmaxf(A.x, a2.x);
                float dy = fminf(Bv.x, b2.x) - fmaxf(A.y, a2.y);
                float dx = fminf(Bv.y, b2.y) - fmaxf(A.z, a2.z);
                dz = fmaxf(dz, 0.0f); dy = fmaxf(dy, 0.0f); dx = fmaxf(dx, 0.0f);
                float inter = (dz*dy)*dx;
                float uni   = (Bv.z + b2.z) - inter;
                bool s = (inter > 0.25f*uni) && (j > i);
                bits |= ((unsigned long long)s) << jj;
            }
        }
        g_mask[b][i][w] = bits;
    }
}

// serial greedy reduce, one warp per batch. ffs-skip over suppressed bits:
// only kept boxes cost serial steps. Per-lane acc holds remv word `lane`.
__global__ void k_nms() {
    __shared__ unsigned long long diag[TOPK];   // 16 KB: row i's own word
    int b = blockIdx.x;
    int lane = threadIdx.x;
    for (int k = lane; k < TOPK; k += 32)
        diag[k] = g_mask[b][k][k >> 6];
    __syncwarp();
    unsigned long long acc = 0ull;
    for (int c = 0; c < NW; c++) {
        unsigned long long cur = __shfl_sync(0xffffffffu, acc, c);
        unsigned long long avail = ~cur;
        unsigned long long kw = 0ull;
        while (avail) {
            int bpos = __ffsll((long long)avail) - 1;     // next kept box
            unsigned long long m = diag[(c << 6) + bpos]; // broadcast LDS
            kw |= 1ull << bpos;
            avail &= ~m;
            avail &= ~(1ull << bpos);
            acc |= g_mask[b][(c << 6) + bpos][lane];      // latency-tolerant
        }
        if (lane == 0) g_keep[b][c] = kw;
    }
}

__global__ void k_final(float* __restrict__ out) {
    int t = blockIdx.x * blockDim.x + threadIdx.x;
    if (t >= BATCH * TOPK) return;
    int b = t / TOPK, r = t - b * TOPK;
    if (!((g_keep[b][r >> 6] >> (r & 63)) & 1ull)) {
        float* o = out + (size_t)t * 7;
        #pragma unroll
        for (int q = 0; q < 7; q++) o[q] = 0.0f;
    }
}

extern "C" void kernel_launch(void* const* d_in, const int* in_sizes, int n_in,
                              void* d_out, int out_size) {
    const float* bb = (const float*)d_in[0];   // (2,6,64,96,96)
    const float* sc = (const float*)d_in[1];   // (2,64,96,96)
    if (n_in >= 2 && in_sizes[0] < in_sizes[1]) {   // defensive: order by size
        const float* tmp = bb; bb = sc; sc = tmp;
    }
    float* out = (float*)d_out;

    k_init<<<(BATCH*NB + 255)/256, 256>>>();
    k_hist<<<dim3(96, BATCH), 256>>>(sc);
    k_select<<<BATCH, 1024>>>();
    k_compact<<<dim3(96, BATCH), 256>>>(sc);
    k_sortgather<<<BATCH, 1024>>>(bb, out);
    k_mask<<<dim3(TOPK/32, BATCH), 256>>>();
    k_nms<<<BATCH, 32>>>();
    k_final<<<(BATCH*TOPK + 255)/256, 256>>>(out);
}